// round 9
// baseline (speedup 1.0000x reference)
#include <cuda_runtime.h>
#include <cstdint>

#define NEG_INF __int_as_float(0xff800000)

static __device__ __forceinline__ float max5(float a, float b, float c, float d, float e) {
    return fmaxf(fmaxf(a, fmaxf(b, c)), fmaxf(d, e));
}

// Hex maxpool, SIZE=2, STRIDE=1, plane = 256x256 fp32.
//   even w: col w rows [h-2,h+2]; cols w+-1 rows [h-2,h+1]; cols w+-2 rows [h-1,h+1]
//   odd  w: col w rows [h-2,h+2]; cols w+-1 rows [h-1,h+2]; cols w+-2 rows [h-1,h+1]
//
// One warp per 256-wide strip of 64 rows; lane owns 8 columns.
// BOTH directions are engine-driven 4KB bursts:
//   Reads : cp.async.bulk (TMA 1D) of 4-row groups into a 4-slot smem ring,
//           mbarrier completion, ~3 groups (12KB) in flight per warp.
//   Writes: 4 rows staged in smem, fired as 4KB cp.async.bulk bursts,
//           double-buffered (proven in R6: +5% DRAM efficiency vs STG).
// Row groups: G1..G15 cover local rows 4..63. Rows -2..3 and tail rows 64,65
// come via clamped LDG into registers (clamp == -inf pad for max, verified R8).
__global__ __launch_bounds__(128, 2)
void hexpool_kernel(const float* __restrict__ x, float* __restrict__ y) {
    extern __shared__ __align__(16) float smem[];   // 4 warps * 24KB
    __shared__ uint64_t mbar_s[4][4];

    const int wid  = threadIdx.x >> 5;
    const int lane = threadIdx.x & 31;
    const int warp_global = blockIdx.x * 4 + wid;
    const int img   = warp_global >> 2;   // 1024 planes (N*C)
    const int chunk = warp_global & 3;    // 4 chunks of 64 rows
    const int h0    = chunk * 64;

    float* rd  = smem + wid * 6144;   // read ring: 4 slots x 4 rows x 256 floats
    float* ost = rd + 4096;           // store stage: 2 bufs x 4 rows x 256 floats
    const uint32_t rd_b  = (uint32_t)__cvta_generic_to_shared(rd);
    const uint32_t ost_b = (uint32_t)__cvta_generic_to_shared(ost);
    uint32_t mb[4];
    #pragma unroll
    for (int s = 0; s < 4; ++s)
        mb[s] = (uint32_t)__cvta_generic_to_shared(&mbar_s[wid][s]);

    if (lane == 0) {
        #pragma unroll
        for (int s = 0; s < 4; ++s)
            asm volatile("mbarrier.init.shared.b64 [%0], 1;" :: "r"(mb[s]) : "memory");
        asm volatile("fence.proxy.async.shared::cta;" ::: "memory");
    }
    __syncthreads();

    const float* inp = x + (size_t)img * 65536;
    const float* inl = inp + lane * 8;
    float* outbase   = y + (size_t)img * 65536;

    // Register window: row m in slot (m+2)&7 (compile-time under 8x unroll).
    float win[8][8];
    float treg[2][8];   // tail rows 64,65 (clamped)

    auto clamp_row = [&](int m) {
        int g = h0 + m;
        return g < 0 ? 0 : (g > 255 ? 255 : g);
    };
    auto load_row_g = [&](int m, float* dst) {
        const float* p = inl + (size_t)clamp_row(m) * 256;
        const float4 a = *reinterpret_cast<const float4*>(p);
        const float4 b = *reinterpret_cast<const float4*>(p + 4);
        dst[0] = a.x; dst[1] = a.y; dst[2] = a.z; dst[3] = a.w;
        dst[4] = b.x; dst[5] = b.y; dst[6] = b.z; dst[7] = b.w;
    };

    // Group G (1..15) = local rows 4G..4G+3, ring slot (G-1)&3,
    // barrier parity for its wait = ((G-1)>>2)&1.
    auto issue_group = [&](int H) {
        if (H <= 15 && lane == 0) {
            const uint32_t bar = mb[(H - 1) & 3];
            const uint32_t dst = rd_b + (uint32_t)(((H - 1) & 3) * 4096);
            const float* src = inp + (size_t)(h0 + 4 * H) * 256;
            asm volatile("mbarrier.arrive.expect_tx.shared.b64 _, [%0], %1;"
                         :: "r"(bar), "r"(4096u) : "memory");
            asm volatile(
                "cp.async.bulk.shared::cluster.global.mbarrier::complete_tx::bytes "
                "[%0], [%1], %2, [%3];"
                :: "r"(dst), "l"(src), "r"(4096u), "r"(bar) : "memory");
        }
    };
    auto wait_group_rd = [&](int G) {
        if (G <= 15) {
            const uint32_t bar = mb[(G - 1) & 3];
            const uint32_t ph  = (uint32_t)(((G - 1) >> 2) & 1);
            asm volatile(
                "{\n\t"
                ".reg .pred P;\n\t"
                "W%=:\n\t"
                "mbarrier.try_wait.parity.acquire.cta.shared::cta.b64 P, [%0], %1, 0x989680;\n\t"
                "@P bra D%=;\n\t"
                "bra W%=;\n\t"
                "D%=:\n\t"
                "}"
                :: "r"(bar), "r"(ph) : "memory");
        }
    };
    auto pull_row = [&](int r, float* dst) {   // r in [4,63]
        const float* s = rd + ((((r >> 2) - 1) & 3) * 1024 + (r & 3) * 256) + lane * 8;
        const float4 a = *reinterpret_cast<const float4*>(s);
        const float4 b = *reinterpret_cast<const float4*>(s + 4);
        dst[0] = a.x; dst[1] = a.y; dst[2] = a.z; dst[3] = a.w;
        dst[4] = b.x; dst[5] = b.y; dst[6] = b.z; dst[7] = b.w;
    };

    // Prologue: rows -2..3 -> win slots 0..5; tail rows 64,65 -> treg;
    // launch read groups G1..G3 (G4 issued at l=0).
    #pragma unroll
    for (int m = -2; m <= 3; ++m) load_row_g(m, win[(m + 2) & 7]);
    load_row_g(64, treg[0]);
    load_row_g(65, treg[1]);
    issue_group(1);
    issue_group(2);
    issue_group(3);

    for (int hh = 0; hh < 64; hh += 8) {
        #pragma unroll
        for (int u = 0; u < 8; ++u) {
            const int l = hh + u;

            if ((u & 3) == 0) {
                // Store stage reuse: allow at most 1 pending store burst.
                asm volatile("cp.async.bulk.wait_group 1;");
                // Rows l+4..l+7 = group l/4+1 arrive now; keep 3 groups ahead.
                wait_group_rd(l / 4 + 1);
                issue_group(l / 4 + 4);
            }

            // Pull row l+4 into win slot (l+6)&7 = (u+6)&7 (consumed at l+2).
            if (l <= 59)           pull_row(l + 4, win[(u + 6) & 7]);
            else if (l <= 61) {
                #pragma unroll
                for (int j = 0; j < 8; ++j) win[(u + 6) & 7][j] = treg[l - 60][j];
            }

            const int s0 = (u + 0) & 7;  // row l-2
            const int s1 = (u + 1) & 7;  // row l-1
            const int sc = (u + 2) & 7;  // row l
            const int s3 = (u + 3) & 7;  // row l+1
            const int s4 = (u + 4) & 7;  // row l+2

            float m3[8], A[8], m5v[8];
            #pragma unroll
            for (int j = 0; j < 8; ++j)
                m3[j] = fmaxf(fmaxf(win[s1][j], win[sc][j]), win[s3][j]);

            // parity of global col = j&1.
            //   odd  w: A = rows [h-2,h+1] = max(m3, r_{l-2})
            //   even w: A = rows [h-1,h+2] = max(m3, r_{l+2})
            //   m5 = 5-row max = max(A, remaining row)
            #pragma unroll
            for (int j = 0; j < 8; ++j) {
                if (j & 1) { A[j]   = fmaxf(m3[j], win[s0][j]);
                             m5v[j] = fmaxf(A[j], win[s4][j]); }
                else       { A[j]   = fmaxf(m3[j], win[s4][j]);
                             m5v[j] = fmaxf(A[j], win[s0][j]); }
            }

            // Horizontal halo across lanes
            float A_l   = __shfl_up_sync(0xffffffffu, A[7], 1);
            float m3_l2 = __shfl_up_sync(0xffffffffu, m3[6], 1);
            float m3_l1 = __shfl_up_sync(0xffffffffu, m3[7], 1);
            float A_r   = __shfl_down_sync(0xffffffffu, A[0], 1);
            float m3_r1 = __shfl_down_sync(0xffffffffu, m3[0], 1);
            float m3_r2 = __shfl_down_sync(0xffffffffu, m3[1], 1);
            if (lane == 0)  { A_l = NEG_INF; m3_l1 = NEG_INF; m3_l2 = NEG_INF; }
            if (lane == 31) { A_r = NEG_INF; m3_r1 = NEG_INF; m3_r2 = NEG_INF; }

            float4 v0, v1;
            v0.x = max5(m5v[0], A_l,  A[1], m3_l2, m3[2]);
            v0.y = max5(m5v[1], A[0], A[2], m3_l1, m3[3]);
            v0.z = max5(m5v[2], A[1], A[3], m3[0], m3[4]);
            v0.w = max5(m5v[3], A[2], A[4], m3[1], m3[5]);
            v1.x = max5(m5v[4], A[3], A[5], m3[2], m3[6]);
            v1.y = max5(m5v[5], A[4], A[6], m3[3], m3[7]);
            v1.z = max5(m5v[6], A[5], A[7], m3[4], m3_r1);
            v1.w = max5(m5v[7], A[6], A_r,  m3[5], m3_r2);

            // Stage the row; buf = (l>>2)&1.
            float* st = ost + ((l >> 2) & 1) * 1024 + (l & 3) * 256 + lane * 8;
            *reinterpret_cast<float4*>(st)     = v0;
            *reinterpret_cast<float4*>(st + 4) = v1;

            if ((u & 3) == 3) {
                // 4 rows (l-3..l) staged -> one 4KB bulk store burst.
                __syncwarp();
                if (lane == 0) {
                    asm volatile("fence.proxy.async.shared::cta;");
                    const uint32_t src = ost_b + (uint32_t)(((l >> 2) & 1) * 4096);
                    float* dst = outbase + (size_t)(h0 + l - 3) * 256;
                    asm volatile(
                        "cp.async.bulk.global.shared::cta.bulk_group [%0], [%1], 4096;"
                        :: "l"(dst), "r"(src) : "memory");
                    asm volatile("cp.async.bulk.commit_group;");
                }
            }
        }
    }

    // Drain outstanding bulk stores, then invalidate the warp's barriers.
    asm volatile("cp.async.bulk.wait_group 0;");
    __syncwarp();
    if (lane == 0) {
        #pragma unroll
        for (int s = 0; s < 4; ++s)
            asm volatile("mbarrier.inval.shared.b64 [%0];" :: "r"(mb[s]) : "memory");
    }
}

extern "C" void kernel_launch(void* const* d_in, const int* in_sizes, int n_in,
                              void* d_out, int out_size) {
    const float* x = (const float*)d_in[0];
    float*       y = (float*)d_out;
    // 4 warps * 24KB dynamic smem = 96KB per CTA -> 2 CTAs/SM.
    cudaFuncSetAttribute(hexpool_kernel,
                         cudaFuncAttributeMaxDynamicSharedMemorySize, 98304);
    // 1024 planes * 4 chunks = 4096 warps; 4 warps/block -> 1024 blocks
    hexpool_kernel<<<1024, 128, 98304>>>(x, y);
}